// round 3
// baseline (speedup 1.0000x reference)
#include <cuda_runtime.h>
#include <cuda_bf16.h>

// 2-layer GCN: out = Ahat(relu(Ahat(x@W1)+b1) @ W2) + b2
// Ahat = sym-normalized adjacency with self loops.
// counting-sort edges by dst -> segment reduction (warp/node), fp32 SGEMMs.
// edge_index dtype (int32 vs int64) detected on-device (JAX x64 demotion).

#define NN 50000
#define NE 800000
#define ET (NN + NE)
#define FIN 128
#define D1  128
#define NCLS 64

// ---- device scratch (static, no allocation) ----
__device__ float g_h1[NN * D1];
__device__ float g_a1[NN * D1];
__device__ float g_h2[NN * NCLS];
__device__ int   g_deg[NN];
__device__ float g_dis[NN];
__device__ int   g_off[NN + 1];
__device__ int   g_cnt[NN];
__device__ int   g_ssrc[ET];
__device__ float g_snorm[ET];
__device__ int   g_is64;

// ---------------------------------------------------------------------------
// dtype probe: if edge_index is int64 (values < 2^31), every odd 32-bit word
// of the raw buffer is 0. Random int32 indices in [0,50000) won't be all-zero
// across 512 sampled odd words.
__global__ void detect_kernel(const int* __restrict__ raw) {
    __shared__ int nz;
    if (threadIdx.x == 0) nz = 0;
    __syncthreads();
    for (int i = threadIdx.x; i < 512; i += blockDim.x)
        if (raw[2 * i + 1] != 0) atomicOr(&nz, 1);
    __syncthreads();
    if (threadIdx.x == 0) g_is64 = (nz == 0) ? 1 : 0;
}

__device__ __forceinline__ int edge_at(const void* raw, int idx) {
    if (g_is64) return (int)((const long long*)raw)[idx];
    return ((const int*)raw)[idx];
}

__global__ void init_kernel() {
    int i = blockIdx.x * blockDim.x + threadIdx.x;
    if (i < NN) { g_deg[i] = 0; g_cnt[i] = 0; }
}

__global__ void degree_kernel(const void* __restrict__ ei) {
    int e = blockIdx.x * blockDim.x + threadIdx.x;
    if (e < NE) {
        int d = edge_at(ei, NE + e);
        atomicAdd(&g_deg[d], 1);
    }
}

__global__ void dis_kernel() {
    int i = blockIdx.x * blockDim.x + threadIdx.x;
    if (i < NN) {
        int d = g_deg[i] + 1;          // +1 self loop
        g_deg[i] = d;
        g_dis[i] = rsqrtf((float)d);
    }
}

// single-block exclusive scan over g_deg -> g_off
__global__ void scan_kernel() {
    __shared__ int warp_sums[32];
    __shared__ int carry;
    int tid = threadIdx.x, lane = tid & 31, w = tid >> 5;
    if (tid == 0) carry = 0;
    __syncthreads();
    for (int base = 0; base < NN; base += 1024) {
        int i = base + tid;
        int v = (i < NN) ? g_deg[i] : 0;
        int x = v;
        #pragma unroll
        for (int dlt = 1; dlt < 32; dlt <<= 1) {
            int t = __shfl_up_sync(0xffffffffu, x, dlt);
            if (lane >= dlt) x += t;
        }
        if (lane == 31) warp_sums[w] = x;
        __syncthreads();
        if (w == 0) {
            int y = warp_sums[lane];
            #pragma unroll
            for (int dlt = 1; dlt < 32; dlt <<= 1) {
                int t = __shfl_up_sync(0xffffffffu, y, dlt);
                if (lane >= dlt) y += t;
            }
            warp_sums[lane] = y;
        }
        __syncthreads();
        int excl = x - v + (w > 0 ? warp_sums[w - 1] : 0) + carry;
        if (i < NN) g_off[i] = excl;
        __syncthreads();
        if (tid == 0) carry += warp_sums[31];
        __syncthreads();
    }
    if (threadIdx.x == 0) g_off[NN] = carry;   // == ET
}

__global__ void scatter_kernel(const void* __restrict__ ei) {
    int e = blockIdx.x * blockDim.x + threadIdx.x;
    if (e >= ET) return;
    int s, d;
    if (e < NE) { s = edge_at(ei, e); d = edge_at(ei, NE + e); }
    else        { s = d = e - NE; }
    int pos = g_off[d] + atomicAdd(&g_cnt[d], 1);
    g_ssrc[pos]  = s;
    g_snorm[pos] = g_dis[s] * g_dis[d];
}

// ---------------------------------------------------------------------------
// fp32 SGEMM, K=128, BM=128, BK=16, 256 threads.
__global__ void __launch_bounds__(256) sgemm1(
    const float* __restrict__ A, const float* __restrict__ B, int M)
{
    constexpr int BM = 128, BN = 128, BK = 16, K = 128, TM = 8, TN = 8;
    __shared__ float As[BK][BM];
    __shared__ float Bs[BK][BN];

    const int tid = threadIdx.x;
    const int block_row = blockIdx.x * BM;
    const int tx = tid % (BN / TN);
    const int ty = tid / (BN / TN);

    float acc[TM][TN];
    #pragma unroll
    for (int i = 0; i < TM; i++)
        #pragma unroll
        for (int j = 0; j < TN; j++) acc[i][j] = 0.f;

    const int a_r = tid / 4;
    const int a_c = (tid % 4) * 4;
    const int b_r = tid / (BN / 4);
    const int b_c = (tid % (BN / 4)) * 4;

    for (int k0 = 0; k0 < K; k0 += BK) {
        #pragma unroll
        for (int it = 0; it < 2; it++) {
            int r = a_r + it * 64;
            int grow = block_row + r;
            float4 v = make_float4(0.f, 0.f, 0.f, 0.f);
            if (grow < M) v = *(const float4*)&A[(size_t)grow * K + k0 + a_c];
            As[a_c + 0][r] = v.x;
            As[a_c + 1][r] = v.y;
            As[a_c + 2][r] = v.z;
            As[a_c + 3][r] = v.w;
        }
        #pragma unroll
        for (int it = 0; it < 2; it++) {
            int r = b_r + it * 8;
            *(float4*)&Bs[r][b_c] = *(const float4*)&B[(size_t)(k0 + r) * BN + b_c];
        }
        __syncthreads();

        #pragma unroll
        for (int k = 0; k < BK; k++) {
            float ra[TM], rb[TN];
            #pragma unroll
            for (int i = 0; i < TM; i++) ra[i] = As[k][ty * TM + i];
            #pragma unroll
            for (int j = 0; j < TN; j++) rb[j] = Bs[k][tx * TN + j];
            #pragma unroll
            for (int i = 0; i < TM; i++)
                #pragma unroll
                for (int j = 0; j < TN; j++)
                    acc[i][j] = fmaf(ra[i], rb[j], acc[i][j]);
        }
        __syncthreads();
    }

    #pragma unroll
    for (int i = 0; i < TM; i++) {
        int grow = block_row + ty * TM + i;
        if (grow < M) {
            #pragma unroll
            for (int j = 0; j < TN; j += 4) {
                float4 v = make_float4(acc[i][j], acc[i][j + 1],
                                       acc[i][j + 2], acc[i][j + 3]);
                *(float4*)&g_h1[(size_t)grow * BN + tx * TN + j] = v;
            }
        }
    }
}

__global__ void __launch_bounds__(256) sgemm2(
    const float* __restrict__ B, int M)
{
    constexpr int BM = 128, BN = 64, BK = 16, K = 128, TM = 8, TN = 4;
    __shared__ float As[BK][BM];
    __shared__ float Bs[BK][BN];

    const int tid = threadIdx.x;
    const int block_row = blockIdx.x * BM;
    const int tx = tid % (BN / TN);
    const int ty = tid / (BN / TN);

    float acc[TM][TN];
    #pragma unroll
    for (int i = 0; i < TM; i++)
        #pragma unroll
        for (int j = 0; j < TN; j++) acc[i][j] = 0.f;

    const int a_r = tid / 4;
    const int a_c = (tid % 4) * 4;
    const int b_r = tid / (BN / 4);
    const int b_c = (tid % (BN / 4)) * 4;

    for (int k0 = 0; k0 < K; k0 += BK) {
        #pragma unroll
        for (int it = 0; it < 2; it++) {
            int r = a_r + it * 64;
            int grow = block_row + r;
            float4 v = make_float4(0.f, 0.f, 0.f, 0.f);
            if (grow < M) v = *(const float4*)&g_a1[(size_t)grow * K + k0 + a_c];
            As[a_c + 0][r] = v.x;
            As[a_c + 1][r] = v.y;
            As[a_c + 2][r] = v.z;
            As[a_c + 3][r] = v.w;
        }
        {
            int r = b_r;
            *(float4*)&Bs[r][b_c] = *(const float4*)&B[(size_t)(k0 + r) * BN + b_c];
        }
        __syncthreads();

        #pragma unroll
        for (int k = 0; k < BK; k++) {
            float ra[TM], rb[TN];
            #pragma unroll
            for (int i = 0; i < TM; i++) ra[i] = As[k][ty * TM + i];
            #pragma unroll
            for (int j = 0; j < TN; j++) rb[j] = Bs[k][tx * TN + j];
            #pragma unroll
            for (int i = 0; i < TM; i++)
                #pragma unroll
                for (int j = 0; j < TN; j++)
                    acc[i][j] = fmaf(ra[i], rb[j], acc[i][j]);
        }
        __syncthreads();
    }

    #pragma unroll
    for (int i = 0; i < TM; i++) {
        int grow = block_row + ty * TM + i;
        if (grow < M) {
            float4 v = make_float4(acc[i][0], acc[i][1], acc[i][2], acc[i][3]);
            *(float4*)&g_h2[(size_t)grow * BN + tx * TN] = v;
        }
    }
}

// ---------------------------------------------------------------------------
// Segment aggregation: warp per node.
__global__ void __launch_bounds__(256) agg128_relu(
    const float* __restrict__ bias)
{
    int gw = (blockIdx.x * blockDim.x + threadIdx.x) >> 5;
    int lane = threadIdx.x & 31;
    if (gw >= NN) return;
    int beg = g_off[gw], end = g_off[gw + 1];

    float4 acc = make_float4(0.f, 0.f, 0.f, 0.f);
    for (int base = beg; base < end; base += 32) {
        int idx = base + lane;
        int s = 0; float nm = 0.f;
        if (idx < end) { s = g_ssrc[idx]; nm = g_snorm[idx]; }
        int cnt = min(32, end - base);
        for (int j = 0; j < cnt; j++) {
            int   sj = __shfl_sync(0xffffffffu, s,  j);
            float nj = __shfl_sync(0xffffffffu, nm, j);
            float4 v = *(const float4*)(g_h1 + (size_t)sj * 128 + lane * 4);
            acc.x = fmaf(nj, v.x, acc.x);
            acc.y = fmaf(nj, v.y, acc.y);
            acc.z = fmaf(nj, v.z, acc.z);
            acc.w = fmaf(nj, v.w, acc.w);
        }
    }
    float4 bb = *(const float4*)(bias + lane * 4);
    acc.x = fmaxf(acc.x + bb.x, 0.f);
    acc.y = fmaxf(acc.y + bb.y, 0.f);
    acc.z = fmaxf(acc.z + bb.z, 0.f);
    acc.w = fmaxf(acc.w + bb.w, 0.f);
    *(float4*)(g_a1 + (size_t)gw * 128 + lane * 4) = acc;
}

__global__ void __launch_bounds__(256) agg64_out(
    const float* __restrict__ bias, float* __restrict__ OUT)
{
    int gw = (blockIdx.x * blockDim.x + threadIdx.x) >> 5;
    int lane = threadIdx.x & 31;
    if (gw >= NN) return;
    int beg = g_off[gw], end = g_off[gw + 1];

    float2 acc = make_float2(0.f, 0.f);
    for (int base = beg; base < end; base += 32) {
        int idx = base + lane;
        int s = 0; float nm = 0.f;
        if (idx < end) { s = g_ssrc[idx]; nm = g_snorm[idx]; }
        int cnt = min(32, end - base);
        for (int j = 0; j < cnt; j++) {
            int   sj = __shfl_sync(0xffffffffu, s,  j);
            float nj = __shfl_sync(0xffffffffu, nm, j);
            float2 v = *(const float2*)(g_h2 + (size_t)sj * 64 + lane * 2);
            acc.x = fmaf(nj, v.x, acc.x);
            acc.y = fmaf(nj, v.y, acc.y);
        }
    }
    float2 bb = *(const float2*)(bias + lane * 2);
    acc.x += bb.x; acc.y += bb.y;
    *(float2*)(OUT + (size_t)gw * 64 + lane * 2) = acc;
}

// ---------------------------------------------------------------------------
extern "C" void kernel_launch(void* const* d_in, const int* in_sizes, int n_in,
                              void* d_out, int out_size) {
    const float* x  = (const float*)d_in[0];
    const void*  ei = d_in[1];
    const float* W1 = (const float*)d_in[2];
    const float* b1 = (const float*)d_in[3];
    const float* W2 = (const float*)d_in[4];
    const float* b2 = (const float*)d_in[5];
    float*       out = (float*)d_out;

    const int TB = 256;
    detect_kernel<<<1, 256>>>((const int*)ei);
    init_kernel<<<(NN + TB - 1) / TB, TB>>>();
    degree_kernel<<<(NE + TB - 1) / TB, TB>>>(ei);
    dis_kernel<<<(NN + TB - 1) / TB, TB>>>();
    scan_kernel<<<1, 1024>>>();
    scatter_kernel<<<(ET + TB - 1) / TB, TB>>>(ei);

    sgemm1<<<(NN + 127) / 128, 256>>>(x, W1, NN);
    agg128_relu<<<(NN * 32 + TB - 1) / TB, TB>>>(b1);

    sgemm2<<<(NN + 127) / 128, 256>>>(W2, NN);
    agg64_out<<<(NN * 32 + TB - 1) / TB, TB>>>(b2, out);
}

// round 4
// speedup vs baseline: 1.0898x; 1.0898x over previous
#include <cuda_runtime.h>
#include <cuda_bf16.h>

// 2-layer GCN: out = Ahat(relu(Ahat(x@W1)+b1) @ W2) + b2
// counting-sort edges by dst -> segment reduction (warp/node),
// fp32 SGEMMs using packed fma.rn.f32x2 (FFMA2).

#define NN 50000
#define NE 800000
#define ET (NN + NE)
#define FIN 128
#define D1  128
#define NCLS 64

// ---- device scratch (static, no allocation) ----
__device__ float g_h1[NN * D1];
__device__ float g_a1[NN * D1];
__device__ float g_h2[NN * NCLS];
__device__ int   g_deg[NN];
__device__ float g_dis[NN];
__device__ int   g_off[NN + 1];
__device__ int   g_cnt[NN];
__device__ int2  g_edge[ET];     // (src, __float_as_int(norm))
__device__ int   g_is64;

// ---- packed f32x2 helpers ----
__device__ __forceinline__ unsigned long long pack2(float lo, float hi) {
    unsigned long long r;
    asm("mov.b64 %0, {%1, %2};" : "=l"(r) : "f"(lo), "f"(hi));
    return r;
}
__device__ __forceinline__ void fma2(unsigned long long& d,
                                     unsigned long long a,
                                     unsigned long long b) {
    asm("fma.rn.f32x2 %0, %1, %2, %3;" : "=l"(d) : "l"(a), "l"(b), "l"(d));
}
__device__ __forceinline__ float lo32(unsigned long long v) {
    return __uint_as_float((unsigned)v);
}
__device__ __forceinline__ float hi32(unsigned long long v) {
    return __uint_as_float((unsigned)(v >> 32));
}

// ---------------------------------------------------------------------------
// init cnt/deg; block 0 probes edge dtype (int64 -> odd 32-bit words all 0)
__global__ void init_detect_kernel(const int* __restrict__ raw) {
    int i = blockIdx.x * blockDim.x + threadIdx.x;
    if (i < NN) { g_deg[i] = 0; g_cnt[i] = 0; }
    if (blockIdx.x == 0) {
        __shared__ int nz;
        if (threadIdx.x == 0) nz = 0;
        __syncthreads();
        for (int k = threadIdx.x; k < 512; k += blockDim.x)
            if (raw[2 * k + 1] != 0) atomicOr(&nz, 1);
        __syncthreads();
        if (threadIdx.x == 0) g_is64 = (nz == 0) ? 1 : 0;
    }
}

__device__ __forceinline__ int edge_at(const void* raw, int idx) {
    if (g_is64) return (int)((const long long*)raw)[idx];
    return ((const int*)raw)[idx];
}

__global__ void degree_kernel(const void* __restrict__ ei) {
    int e = blockIdx.x * blockDim.x + threadIdx.x;
    if (e < NE) atomicAdd(&g_deg[edge_at(ei, NE + e)], 1);
}

// single-block: d = deg+1 (self loop), dis = rsqrt(d), exclusive scan -> g_off
__global__ void scan_dis_kernel() {
    __shared__ int warp_sums[32];
    __shared__ int carry;
    int tid = threadIdx.x, lane = tid & 31, w = tid >> 5;
    if (tid == 0) carry = 0;
    __syncthreads();
    for (int base = 0; base < NN; base += 1024) {
        int i = base + tid;
        int v = 0;
        if (i < NN) {
            v = g_deg[i] + 1;
            g_dis[i] = rsqrtf((float)v);
        }
        int x = v;
        #pragma unroll
        for (int dlt = 1; dlt < 32; dlt <<= 1) {
            int t = __shfl_up_sync(0xffffffffu, x, dlt);
            if (lane >= dlt) x += t;
        }
        if (lane == 31) warp_sums[w] = x;
        __syncthreads();
        if (w == 0) {
            int y = warp_sums[lane];
            #pragma unroll
            for (int dlt = 1; dlt < 32; dlt <<= 1) {
                int t = __shfl_up_sync(0xffffffffu, y, dlt);
                if (lane >= dlt) y += t;
            }
            warp_sums[lane] = y;
        }
        __syncthreads();
        int excl = x - v + (w > 0 ? warp_sums[w - 1] : 0) + carry;
        if (i < NN) g_off[i] = excl;
        __syncthreads();
        if (tid == 0) carry += warp_sums[31];
        __syncthreads();
    }
    if (threadIdx.x == 0) g_off[NN] = carry;   // == ET
}

__global__ void scatter_kernel(const void* __restrict__ ei) {
    int e = blockIdx.x * blockDim.x + threadIdx.x;
    if (e >= ET) return;
    int s, d;
    if (e < NE) { s = edge_at(ei, e); d = edge_at(ei, NE + e); }
    else        { s = d = e - NE; }
    int pos = g_off[d] + atomicAdd(&g_cnt[d], 1);
    g_edge[pos] = make_int2(s, __float_as_int(g_dis[s] * g_dis[d]));
}

// ---------------------------------------------------------------------------
// fp32 SGEMM (f32x2 mainloop), K=128, BM=128, BK=16, 256 threads.
__global__ void __launch_bounds__(256) sgemm1(
    const float* __restrict__ A, const float* __restrict__ B, int M)
{
    constexpr int BM = 128, BN = 128, BK = 16, K = 128, TM = 8, TN = 8;
    __shared__ float As[BK][BM];
    __shared__ float Bs[BK][BN];

    const int tid = threadIdx.x;
    const int block_row = blockIdx.x * BM;
    const int tx = tid % (BN / TN);
    const int ty = tid / (BN / TN);

    unsigned long long acc2[TM][TN / 2];
    #pragma unroll
    for (int i = 0; i < TM; i++)
        #pragma unroll
        for (int j = 0; j < TN / 2; j++) acc2[i][j] = 0ull;

    const int a_r = tid / 4;
    const int a_c = (tid % 4) * 4;
    const int b_r = tid / (BN / 4);
    const int b_c = (tid % (BN / 4)) * 4;

    for (int k0 = 0; k0 < K; k0 += BK) {
        #pragma unroll
        for (int it = 0; it < 2; it++) {
            int r = a_r + it * 64;
            int grow = block_row + r;
            float4 v = make_float4(0.f, 0.f, 0.f, 0.f);
            if (grow < M) v = *(const float4*)&A[(size_t)grow * K + k0 + a_c];
            As[a_c + 0][r] = v.x;
            As[a_c + 1][r] = v.y;
            As[a_c + 2][r] = v.z;
            As[a_c + 3][r] = v.w;
        }
        #pragma unroll
        for (int it = 0; it < 2; it++) {
            int r = b_r + it * 8;
            *(float4*)&Bs[r][b_c] = *(const float4*)&B[(size_t)(k0 + r) * BN + b_c];
        }
        __syncthreads();

        #pragma unroll
        for (int k = 0; k < BK; k++) {
            unsigned long long ra2[TM], rb2[TN / 2];
            #pragma unroll
            for (int i = 0; i < TM; i++) {
                float a = As[k][ty * TM + i];
                ra2[i] = pack2(a, a);
            }
            #pragma unroll
            for (int j = 0; j < TN / 2; j++)
                rb2[j] = *(const unsigned long long*)&Bs[k][tx * TN + 2 * j];
            #pragma unroll
            for (int i = 0; i < TM; i++)
                #pragma unroll
                for (int j = 0; j < TN / 2; j++)
                    fma2(acc2[i][j], ra2[i], rb2[j]);
        }
        __syncthreads();
    }

    #pragma unroll
    for (int i = 0; i < TM; i++) {
        int grow = block_row + ty * TM + i;
        if (grow < M) {
            #pragma unroll
            for (int j = 0; j < TN / 2; j += 2) {
                float4 v = make_float4(lo32(acc2[i][j]), hi32(acc2[i][j]),
                                       lo32(acc2[i][j + 1]), hi32(acc2[i][j + 1]));
                *(float4*)&g_h1[(size_t)grow * BN + tx * TN + 2 * j] = v;
            }
        }
    }
}

__global__ void __launch_bounds__(256) sgemm2(
    const float* __restrict__ B, int M)
{
    constexpr int BM = 128, BN = 64, BK = 16, K = 128, TM = 8, TN = 4;
    __shared__ float As[BK][BM];
    __shared__ float Bs[BK][BN];

    const int tid = threadIdx.x;
    const int block_row = blockIdx.x * BM;
    const int tx = tid % (BN / TN);
    const int ty = tid / (BN / TN);

    unsigned long long acc2[TM][TN / 2];
    #pragma unroll
    for (int i = 0; i < TM; i++)
        #pragma unroll
        for (int j = 0; j < TN / 2; j++) acc2[i][j] = 0ull;

    const int a_r = tid / 4;
    const int a_c = (tid % 4) * 4;
    const int b_r = tid / (BN / 4);
    const int b_c = (tid % (BN / 4)) * 4;

    for (int k0 = 0; k0 < K; k0 += BK) {
        #pragma unroll
        for (int it = 0; it < 2; it++) {
            int r = a_r + it * 64;
            int grow = block_row + r;
            float4 v = make_float4(0.f, 0.f, 0.f, 0.f);
            if (grow < M) v = *(const float4*)&g_a1[(size_t)grow * K + k0 + a_c];
            As[a_c + 0][r] = v.x;
            As[a_c + 1][r] = v.y;
            As[a_c + 2][r] = v.z;
            As[a_c + 3][r] = v.w;
        }
        {
            int r = b_r;
            *(float4*)&Bs[r][b_c] = *(const float4*)&B[(size_t)(k0 + r) * BN + b_c];
        }
        __syncthreads();

        #pragma unroll
        for (int k = 0; k < BK; k++) {
            unsigned long long ra2[TM], rb2[TN / 2];
            #pragma unroll
            for (int i = 0; i < TM; i++) {
                float a = As[k][ty * TM + i];
                ra2[i] = pack2(a, a);
            }
            #pragma unroll
            for (int j = 0; j < TN / 2; j++)
                rb2[j] = *(const unsigned long long*)&Bs[k][tx * TN + 2 * j];
            #pragma unroll
            for (int i = 0; i < TM; i++)
                #pragma unroll
                for (int j = 0; j < TN / 2; j++)
                    fma2(acc2[i][j], ra2[i], rb2[j]);
        }
        __syncthreads();
    }

    #pragma unroll
    for (int i = 0; i < TM; i++) {
        int grow = block_row + ty * TM + i;
        if (grow < M) {
            float4 v = make_float4(lo32(acc2[i][0]), hi32(acc2[i][0]),
                                   lo32(acc2[i][1]), hi32(acc2[i][1]));
            *(float4*)&g_h2[(size_t)grow * BN + tx * TN] = v;
        }
    }
}

// ---------------------------------------------------------------------------
// Segment aggregation: warp per node, warp-uniform edge loads, 4x unroll.
__global__ void __launch_bounds__(256) agg128_relu(
    const float* __restrict__ bias)
{
    int gw = (blockIdx.x * blockDim.x + threadIdx.x) >> 5;
    int lane = threadIdx.x & 31;
    if (gw >= NN) return;
    int beg = g_off[gw], end = g_off[gw + 1];
    int c4 = lane * 4;

    float4 acc = make_float4(0.f, 0.f, 0.f, 0.f);
    int idx = beg;
    for (; idx + 4 <= end; idx += 4) {
        int2 e0 = g_edge[idx + 0];
        int2 e1 = g_edge[idx + 1];
        int2 e2 = g_edge[idx + 2];
        int2 e3 = g_edge[idx + 3];
        float4 v0 = *(const float4*)(g_h1 + (size_t)e0.x * 128 + c4);
        float4 v1 = *(const float4*)(g_h1 + (size_t)e1.x * 128 + c4);
        float4 v2 = *(const float4*)(g_h1 + (size_t)e2.x * 128 + c4);
        float4 v3 = *(const float4*)(g_h1 + (size_t)e3.x * 128 + c4);
        float n0 = __int_as_float(e0.y), n1 = __int_as_float(e1.y);
        float n2 = __int_as_float(e2.y), n3 = __int_as_float(e3.y);
        acc.x = fmaf(n0, v0.x, acc.x); acc.y = fmaf(n0, v0.y, acc.y);
        acc.z = fmaf(n0, v0.z, acc.z); acc.w = fmaf(n0, v0.w, acc.w);
        acc.x = fmaf(n1, v1.x, acc.x); acc.y = fmaf(n1, v1.y, acc.y);
        acc.z = fmaf(n1, v1.z, acc.z); acc.w = fmaf(n1, v1.w, acc.w);
        acc.x = fmaf(n2, v2.x, acc.x); acc.y = fmaf(n2, v2.y, acc.y);
        acc.z = fmaf(n2, v2.z, acc.z); acc.w = fmaf(n2, v2.w, acc.w);
        acc.x = fmaf(n3, v3.x, acc.x); acc.y = fmaf(n3, v3.y, acc.y);
        acc.z = fmaf(n3, v3.z, acc.z); acc.w = fmaf(n3, v3.w, acc.w);
    }
    for (; idx < end; idx++) {
        int2 e = g_edge[idx];
        float n = __int_as_float(e.y);
        float4 v = *(const float4*)(g_h1 + (size_t)e.x * 128 + c4);
        acc.x = fmaf(n, v.x, acc.x); acc.y = fmaf(n, v.y, acc.y);
        acc.z = fmaf(n, v.z, acc.z); acc.w = fmaf(n, v.w, acc.w);
    }
    float4 bb = *(const float4*)(bias + c4);
    acc.x = fmaxf(acc.x + bb.x, 0.f);
    acc.y = fmaxf(acc.y + bb.y, 0.f);
    acc.z = fmaxf(acc.z + bb.z, 0.f);
    acc.w = fmaxf(acc.w + bb.w, 0.f);
    *(float4*)(g_a1 + (size_t)gw * 128 + c4) = acc;
}

__global__ void __launch_bounds__(256) agg64_out(
    const float* __restrict__ bias, float* __restrict__ OUT)
{
    int gw = (blockIdx.x * blockDim.x + threadIdx.x) >> 5;
    int lane = threadIdx.x & 31;
    if (gw >= NN) return;
    int beg = g_off[gw], end = g_off[gw + 1];
    int c2 = lane * 2;

    float2 acc = make_float2(0.f, 0.f);
    int idx = beg;
    for (; idx + 4 <= end; idx += 4) {
        int2 e0 = g_edge[idx + 0];
        int2 e1 = g_edge[idx + 1];
        int2 e2 = g_edge[idx + 2];
        int2 e3 = g_edge[idx + 3];
        float2 v0 = *(const float2*)(g_h2 + (size_t)e0.x * 64 + c2);
        float2 v1 = *(const float2*)(g_h2 + (size_t)e1.x * 64 + c2);
        float2 v2 = *(const float2*)(g_h2 + (size_t)e2.x * 64 + c2);
        float2 v3 = *(const float2*)(g_h2 + (size_t)e3.x * 64 + c2);
        float n0 = __int_as_float(e0.y), n1 = __int_as_float(e1.y);
        float n2 = __int_as_float(e2.y), n3 = __int_as_float(e3.y);
        acc.x = fmaf(n0, v0.x, acc.x); acc.y = fmaf(n0, v0.y, acc.y);
        acc.x = fmaf(n1, v1.x, acc.x); acc.y = fmaf(n1, v1.y, acc.y);
        acc.x = fmaf(n2, v2.x, acc.x); acc.y = fmaf(n2, v2.y, acc.y);
        acc.x = fmaf(n3, v3.x, acc.x); acc.y = fmaf(n3, v3.y, acc.y);
    }
    for (; idx < end; idx++) {
        int2 e = g_edge[idx];
        float n = __int_as_float(e.y);
        float2 v = *(const float2*)(g_h2 + (size_t)e.x * 64 + c2);
        acc.x = fmaf(n, v.x, acc.x); acc.y = fmaf(n, v.y, acc.y);
    }
    float2 bb = *(const float2*)(bias + c2);
    acc.x += bb.x; acc.y += bb.y;
    *(float2*)(OUT + (size_t)gw * 64 + c2) = acc;
}

// ---------------------------------------------------------------------------
extern "C" void kernel_launch(void* const* d_in, const int* in_sizes, int n_in,
                              void* d_out, int out_size) {
    const float* x  = (const float*)d_in[0];
    const void*  ei = d_in[1];
    const float* W1 = (const float*)d_in[2];
    const float* b1 = (const float*)d_in[3];
    const float* W2 = (const float*)d_in[4];
    const float* b2 = (const float*)d_in[5];
    float*       out = (float*)d_out;

    const int TB = 256;
    init_detect_kernel<<<(NN + TB - 1) / TB, TB>>>((const int*)ei);
    degree_kernel<<<(NE + TB - 1) / TB, TB>>>(ei);
    scan_dis_kernel<<<1, 1024>>>();
    scatter_kernel<<<(ET + TB - 1) / TB, TB>>>(ei);

    sgemm1<<<(NN + 127) / 128, 256>>>(x, W1, NN);
    agg128_relu<<<(NN * 32 + TB - 1) / TB, TB>>>(b1);

    sgemm2<<<(NN + 127) / 128, 256>>>(W2, NN);
    agg64_out<<<(NN * 32 + TB - 1) / TB, TB>>>(b2, out);
}